// round 14
// baseline (speedup 1.0000x reference)
#include <cuda_runtime.h>
#include <cuda_fp16.h>
#include <math.h>

#define N_NODES 100000
#define N_EDGES 3200000
#define N_GRAPHS 128
#define SCAN_CHUNKS 98            // ceil(100000/1024)

// ---------------- device scratch ----------------
__device__ int   g_is64;
__device__ int   g_cnt[N_NODES];
__device__ float g_dinv[N_NODES];
__device__ int   g_rowptr[N_NODES + 1];
__device__ int   g_cursor[N_NODES];
__device__ int   g_edge[N_EDGES];           // src only (weights reassociated away)
__device__ uint4 g_h16[N_NODES * 8];        // fp16 dinv-scaled hidden h~1 [N,64]
__device__ uint4 g_h16b[N_NODES * 8];       // fp16 dinv-scaled hidden h~2 [N,64]
__device__ uint4 g_x16[N_NODES * 4];        // fp16 dinv-scaled padded x [N,32]
__device__ float g_psum[N_GRAPHS * 64];
__device__ int   g_start[N_GRAPHS + 1];
__device__ int   g_bsum[128];
__device__ int   g_boff[128];

// ---------------- helpers ----------------
__device__ __forceinline__ int ld_idx(const void* p, long long i) {
    if (g_is64) return (int)((const long long*)p)[i];
    return ((const int*)p)[i];
}

__device__ __forceinline__ void fma8(float* acc, uint4 v, float w) {
    float2 a = __half22float2(*(__half2*)&v.x);
    float2 b = __half22float2(*(__half2*)&v.y);
    float2 c = __half22float2(*(__half2*)&v.z);
    float2 d = __half22float2(*(__half2*)&v.w);
    acc[0] = fmaf(w, a.x, acc[0]); acc[1] = fmaf(w, a.y, acc[1]);
    acc[2] = fmaf(w, b.x, acc[2]); acc[3] = fmaf(w, b.y, acc[3]);
    acc[4] = fmaf(w, c.x, acc[4]); acc[5] = fmaf(w, c.y, acc[5]);
    acc[6] = fmaf(w, d.x, acc[6]); acc[7] = fmaf(w, d.y, acc[7]);
}

// ---------------- prep: dtype probe (thread 0) + zero counters ----------------
__global__ void k_prep(const void* p) {
    int i = blockIdx.x * blockDim.x + threadIdx.x;
    if (i == 0) {
        const long long* q = (const long long*)p;
        int ok64 = 1;
        for (int k = 0; k < 256; k++) {
            long long v = q[k];
            if (v < 0 || v >= (long long)N_NODES) { ok64 = 0; break; }
        }
        g_is64 = ok64;
    }
    if (i < N_NODES) g_cnt[i] = 0;
    if (i < N_GRAPHS * 64) g_psum[i] = 0.f;
}

// ---------------- graph boundaries (batch sorted, no atomics) ----------------
__global__ void k_bound(const void* p) {
    int i = blockIdx.x * blockDim.x + threadIdx.x;
    if (i >= N_NODES) return;
    int b = ld_idx(p, i);
    int prev = (i == 0) ? -1 : ld_idx(p, i - 1);
    for (int g = prev + 1; g <= b; g++) g_start[g] = i;
    if (i == N_NODES - 1)
        for (int g = b + 1; g <= N_GRAPHS; g++) g_start[g] = N_NODES;
}

// ---------------- degree count: 4 edges/thread, fire-and-forget atomics -------
__global__ void k_deg(const void* p) {
    int t = blockIdx.x * blockDim.x + threadIdx.x;
    if (t >= N_EDGES / 4) return;
    int d0, d1, d2, d3;
    if (g_is64) {
        const longlong2* q = (const longlong2*)((const long long*)p + N_EDGES);
        longlong2 a = __ldg(&q[2 * t]);
        longlong2 b = __ldg(&q[2 * t + 1]);
        d0 = (int)a.x; d1 = (int)a.y; d2 = (int)b.x; d3 = (int)b.y;
    } else {
        const int4* q = (const int4*)((const int*)p + N_EDGES);
        int4 v = __ldg(&q[t]);
        d0 = v.x; d1 = v.y; d2 = v.z; d3 = v.w;
    }
    atomicAdd(&g_cnt[d0], 1);
    atomicAdd(&g_cnt[d1], 1);
    atomicAdd(&g_cnt[d2], 1);
    atomicAdd(&g_cnt[d3], 1);
}

// ---------------- multi-block scan ----------------
__global__ __launch_bounds__(1024) void k_scan1() {
    int tid = threadIdx.x;
    int lane = tid & 31, wid = tid >> 5;
    int i = blockIdx.x * 1024 + tid;
    int v = (i < N_NODES) ? g_cnt[i] : 0;
    int x = v;
    #pragma unroll
    for (int off = 1; off < 32; off <<= 1) {
        int t = __shfl_up_sync(0xFFFFFFFFu, x, off);
        if (lane >= off) x += t;
    }
    __shared__ int ws[32];
    if (lane == 31) ws[wid] = x;
    __syncthreads();
    if (wid == 0) {
        int y = ws[lane];
        #pragma unroll
        for (int off = 1; off < 32; off <<= 1) {
            int t = __shfl_up_sync(0xFFFFFFFFu, y, off);
            if (lane >= off) y += t;
        }
        ws[lane] = y;
    }
    __syncthreads();
    int incl = x + (wid > 0 ? ws[wid - 1] : 0);
    if (i < N_NODES) g_rowptr[i] = incl - v;
    if (tid == 1023) g_bsum[blockIdx.x] = incl;
}

__global__ void k_scan2() {
    __shared__ int sh[128];
    int t = threadIdx.x;
    int v = (t < SCAN_CHUNKS) ? g_bsum[t] : 0;
    sh[t] = v;
    __syncthreads();
    #pragma unroll
    for (int off = 1; off < 128; off <<= 1) {
        int u = (t >= off) ? sh[t - off] : 0;
        __syncthreads();
        sh[t] += u;
        __syncthreads();
    }
    if (t < SCAN_CHUNKS) g_boff[t] = sh[t] - v;
    if (t == 127) g_rowptr[N_NODES] = sh[127];
}

// ---------------- scan3: finalize rowptr/cursor/dinv + build x~ = dinv*x ------
__global__ void k_scan3(const float* __restrict__ x) {
    int i = blockIdx.x * blockDim.x + threadIdx.x;
    if (i >= N_NODES) return;
    int r = g_rowptr[i] + g_boff[i >> 10];
    g_rowptr[i] = r;
    g_cursor[i] = r;
    float di = rsqrtf((float)g_cnt[i] + 1.0f);
    g_dinv[i] = di;
    const float4* xr = (const float4*)(x + i * 20);   // 80B row, 16B aligned
    float tmp[20];
    #pragma unroll
    for (int q = 0; q < 5; q++) {
        float4 v = __ldg(&xr[q]);
        tmp[4*q] = v.x; tmp[4*q+1] = v.y; tmp[4*q+2] = v.z; tmp[4*q+3] = v.w;
    }
    unsigned h[16];
    #pragma unroll
    for (int q = 0; q < 10; q++) {
        __half2 hh = __floats2half2_rn(di * tmp[2*q], di * tmp[2*q+1]);
        h[q] = *(unsigned*)&hh;
    }
    #pragma unroll
    for (int q = 10; q < 16; q++) h[q] = 0u;
    uint4* dst = &g_x16[i * 4];
    dst[0] = make_uint4(h[0], h[1], h[2], h[3]);
    dst[1] = make_uint4(h[4], h[5], h[6], h[7]);
    dst[2] = make_uint4(h[8], h[9], h[10], h[11]);
    dst[3] = make_uint4(h[12], h[13], h[14], h[15]);
}

// ---------------- CSR fill: src only ----------------
__global__ void k_fill(const void* p) {
    int t = blockIdx.x * blockDim.x + threadIdx.x;
    if (t >= N_EDGES / 2) return;
    int s0, s1, d0, d1;
    if (g_is64) {
        const longlong2* qs = (const longlong2*)p;
        const longlong2* qd = (const longlong2*)((const long long*)p + N_EDGES);
        longlong2 sv = __ldg(&qs[t]);
        longlong2 dv = __ldg(&qd[t]);
        s0 = (int)sv.x; s1 = (int)sv.y;
        d0 = (int)dv.x; d1 = (int)dv.y;
    } else {
        const int2* qs = (const int2*)p;
        const int2* qd = (const int2*)((const int*)p + N_EDGES);
        int2 sv = __ldg(&qs[t]);
        int2 dv = __ldg(&qd[t]);
        s0 = sv.x; s1 = sv.y;
        d0 = dv.x; d1 = dv.y;
    }
    int p0 = atomicAdd(&g_cursor[d0], 1);
    g_edge[p0] = s0;
    int p1 = atomicAdd(&g_cursor[d1], 1);
    g_edge[p1] = s1;
}

// ---------------- Layer 1 fused: agg20 + mm1 + relu + prescale -> g_h16 -------
// Persistent grid-stride, warp per node. 8 edges per LDG.128 gather on x~.
__global__ __launch_bounds__(256) void k_l1(const float* __restrict__ W1,
                                            const float* __restrict__ b1) {
    __shared__ float Ws[20 * 64];
    __shared__ float bs[64];
    __shared__ float sw[8][32];
    for (int k = threadIdx.x; k < 20 * 64; k += 256) Ws[k] = W1[k];
    if (threadIdx.x < 64) bs[threadIdx.x] = b1[threadIdx.x];
    __syncthreads();
    int warp = threadIdx.x >> 5, lane = threadIdx.x & 31;
    int eg = lane >> 2, fl = lane & 3;
    for (int i = blockIdx.x * 8 + warp; i < N_NODES; i += gridDim.x * 8) {
        int beg = g_rowptr[i], end = g_rowptr[i + 1];
        float acc[8];
        #pragma unroll
        for (int j = 0; j < 8; j++) acc[j] = 0.f;
        for (int e = beg; e < end; e += 16) {
            int e0 = e + eg, e1 = e + 8 + eg;
            int s0 = g_edge[(e0 < end) ? e0 : beg];
            int s1 = g_edge[(e1 < end) ? e1 : beg];
            float w0 = (e0 < end) ? 1.f : 0.f;
            float w1 = (e1 < end) ? 1.f : 0.f;
            uint4 v0 = __ldg(&g_x16[s0 * 4 + fl]);
            uint4 v1 = __ldg(&g_x16[s1 * 4 + fl]);
            fma8(acc, v0, w0);
            fma8(acc, v1, w1);
        }
        #pragma unroll
        for (int j = 0; j < 8; j++) {
            acc[j] += __shfl_xor_sync(0xFFFFFFFFu, acc[j], 4);
            acc[j] += __shfl_xor_sync(0xFFFFFFFFu, acc[j], 8);
            acc[j] += __shfl_xor_sync(0xFFFFFFFFu, acc[j], 16);
        }
        float di = g_dinv[i];
        uint4 sv = g_x16[i * 4 + fl];     // self-loop
        fma8(acc, sv, 1.f);
        #pragma unroll
        for (int j = 0; j < 8; j++) acc[j] *= di;
        if (eg == 0) {
            #pragma unroll
            for (int j = 0; j < 8; j++) sw[warp][fl * 8 + j] = acc[j];
        }
        __syncwarp();
        // mm1: each lane computes output cols 2*lane, 2*lane+1
        float o0 = bs[2 * lane], o1 = bs[2 * lane + 1];
        #pragma unroll
        for (int k = 0; k < 20; k++) {
            float a = sw[warp][k];
            o0 = fmaf(a, Ws[k * 64 + 2 * lane], o0);
            o1 = fmaf(a, Ws[k * 64 + 2 * lane + 1], o1);
        }
        __half2 hh = __floats2half2_rn(di * fmaxf(o0, 0.f), di * fmaxf(o1, 0.f));
        ((unsigned*)g_h16)[i * 32 + lane] = *(unsigned*)&hh;
        __syncwarp();
    }
}

// ---------------- Layer 2 fused: agg64(g_h16) + mm2 -> g_h16b (double buffer) --
__global__ __launch_bounds__(256) void k_l2(const float* __restrict__ W2,
                                            const float* __restrict__ b2) {
    __shared__ float Ws[64 * 64];
    __shared__ float bs[64];
    __shared__ float sw[8][64];
    for (int k = threadIdx.x; k < 64 * 64; k += 256) Ws[k] = W2[k];
    if (threadIdx.x < 64) bs[threadIdx.x] = b2[threadIdx.x];
    __syncthreads();
    int warp = threadIdx.x >> 5, lane = threadIdx.x & 31;
    int eg = lane >> 3, fl = lane & 7;
    for (int i = blockIdx.x * 8 + warp; i < N_NODES; i += gridDim.x * 8) {
        int beg = g_rowptr[i], end = g_rowptr[i + 1];
        float acc[8];
        #pragma unroll
        for (int j = 0; j < 8; j++) acc[j] = 0.f;
        for (int e = beg; e < end; e += 8) {
            int e0 = e + eg, e1 = e + 4 + eg;
            int s0 = g_edge[(e0 < end) ? e0 : beg];
            int s1 = g_edge[(e1 < end) ? e1 : beg];
            float w0 = (e0 < end) ? 1.f : 0.f;
            float w1 = (e1 < end) ? 1.f : 0.f;
            uint4 v0 = __ldg(&g_h16[s0 * 8 + fl]);
            uint4 v1 = __ldg(&g_h16[s1 * 8 + fl]);
            fma8(acc, v0, w0);
            fma8(acc, v1, w1);
        }
        #pragma unroll
        for (int j = 0; j < 8; j++) {
            acc[j] += __shfl_xor_sync(0xFFFFFFFFu, acc[j], 8);
            acc[j] += __shfl_xor_sync(0xFFFFFFFFu, acc[j], 16);
        }
        float di = g_dinv[i];
        uint4 sv = g_h16[i * 8 + fl];     // self-loop
        fma8(acc, sv, 1.f);
        #pragma unroll
        for (int j = 0; j < 8; j++) acc[j] *= di;
        if (eg == 0) {
            #pragma unroll
            for (int j = 0; j < 8; j++) sw[warp][fl * 8 + j] = acc[j];
        }
        __syncwarp();
        float o0 = bs[2 * lane], o1 = bs[2 * lane + 1];
        #pragma unroll 8
        for (int k = 0; k < 64; k++) {
            float a = sw[warp][k];
            o0 = fmaf(a, Ws[k * 64 + 2 * lane], o0);
            o1 = fmaf(a, Ws[k * 64 + 2 * lane + 1], o1);
        }
        __half2 hh = __floats2half2_rn(di * fmaxf(o0, 0.f), di * fmaxf(o1, 0.f));
        ((unsigned*)g_h16b)[i * 32 + lane] = *(unsigned*)&hh;
        __syncwarp();
    }
}

// ---------------- Layer 3: agg64(g_h16b) + pooling (batch sorted) --------------
__global__ __launch_bounds__(256) void k_l3(const void* batch) {
    __shared__ float sacc[64];
    __shared__ int sg;
    int i = (blockIdx.x * blockDim.x + threadIdx.x) >> 5;   // grid exact
    int lane = threadIdx.x & 31;
    int eg = lane >> 3, fl = lane & 7;
    if (threadIdx.x < 64) sacc[threadIdx.x] = 0.f;
    if (threadIdx.x == 0) sg = ld_idx(batch, (blockIdx.x * blockDim.x) >> 5);
    __syncthreads();
    int beg = g_rowptr[i], end = g_rowptr[i + 1];
    float acc[8];
    #pragma unroll
    for (int j = 0; j < 8; j++) acc[j] = 0.f;
    for (int e = beg; e < end; e += 8) {
        int e0 = e + eg, e1 = e + 4 + eg;
        int s0 = g_edge[(e0 < end) ? e0 : beg];
        int s1 = g_edge[(e1 < end) ? e1 : beg];
        float w0 = (e0 < end) ? 1.f : 0.f;
        float w1 = (e1 < end) ? 1.f : 0.f;
        uint4 v0 = __ldg(&g_h16b[s0 * 8 + fl]);
        uint4 v1 = __ldg(&g_h16b[s1 * 8 + fl]);
        fma8(acc, v0, w0);
        fma8(acc, v1, w1);
    }
    #pragma unroll
    for (int j = 0; j < 8; j++) {
        acc[j] += __shfl_xor_sync(0xFFFFFFFFu, acc[j], 8);
        acc[j] += __shfl_xor_sync(0xFFFFFFFFu, acc[j], 16);
    }
    float di = g_dinv[i];
    uint4 sv = g_h16b[i * 8 + fl];
    fma8(acc, sv, 1.f);
    #pragma unroll
    for (int j = 0; j < 8; j++) acc[j] *= di;
    int b = ld_idx(batch, i);
    int uniform = __syncthreads_and(b == sg);
    if (uniform) {
        if (eg == 0) {
            #pragma unroll
            for (int j = 0; j < 8; j++)
                atomicAdd(&sacc[fl * 8 + j], acc[j]);
        }
        __syncthreads();
        if (threadIdx.x < 64)
            atomicAdd(&g_psum[sg * 64 + threadIdx.x], sacc[threadIdx.x]);
    } else {
        if (eg == 0) {
            #pragma unroll
            for (int j = 0; j < 8; j++)
                atomicAdd(&g_psum[b * 64 + fl * 8 + j], acc[j]);
        }
    }
}

// ---------------- final: (mean @ W3 + b3) @ Wl + bl -> log_softmax -------------
__global__ __launch_bounds__(128) void k_final(const float* __restrict__ W3,
                                               const float* __restrict__ b3,
                                               const float* __restrict__ Wl,
                                               const float* __restrict__ bl,
                                               float* __restrict__ out) {
    int g = blockIdx.x;
    int j = threadIdx.x;
    __shared__ float sp[64];
    __shared__ float sf[128];
    int st = g_start[g], en = g_start[g + 1];
    float inv = 1.0f / fmaxf((float)(en - st), 1.0f);
    if (j < 64) sp[j] = g_psum[g * 64 + j] * inv;
    __syncthreads();
    float f = b3[j];
    #pragma unroll 8
    for (int k = 0; k < 64; k++)
        f = fmaf(sp[k], W3[k * 128 + j], f);
    sf[j] = f;
    __syncthreads();
    if (j < 32) {
        float l = -INFINITY;
        if (j < 14) {
            float acc = bl[j];
            #pragma unroll 8
            for (int k = 0; k < 128; k++)
                acc = fmaf(sf[k], Wl[k * 14 + j], acc);
            l = acc;
        }
        float m = l;
        #pragma unroll
        for (int off = 16; off; off >>= 1)
            m = fmaxf(m, __shfl_xor_sync(0xFFFFFFFFu, m, off));
        float ex = (j < 14) ? expf(l - m) : 0.f;
        float s = ex;
        #pragma unroll
        for (int off = 16; off; off >>= 1)
            s += __shfl_xor_sync(0xFFFFFFFFu, s, off);
        if (j < 14) out[g * 14 + j] = l - m - logf(s);
    }
}

// ---------------- launch ----------------
extern "C" void kernel_launch(void* const* d_in, const int* in_sizes, int n_in,
                              void* d_out, int out_size) {
    const float* x     = (const float*)d_in[0];
    const void*  ei    = d_in[1];
    const void*  batch = d_in[2];
    const float* W1 = (const float*)d_in[3];
    const float* b1 = (const float*)d_in[4];
    const float* W2 = (const float*)d_in[5];
    const float* b2 = (const float*)d_in[6];
    const float* W3 = (const float*)d_in[7];
    const float* b3 = (const float*)d_in[8];
    const float* Wl = (const float*)d_in[9];
    const float* bl = (const float*)d_in[10];
    float* out = (float*)d_out;

    const int TB = 256;
    int nblkN = (N_NODES + TB - 1) / TB;
    int nblkW = N_NODES / 8;            // exact: 100000 = 12500 * 8
    int fusedGrid = 592;                // persistent: 4 blocks/SM

    k_prep<<<nblkN, TB>>>(ei);                                      // 1
    k_bound<<<nblkN, TB>>>(batch);                                  // 2
    k_deg<<<(N_EDGES / 4 + TB - 1) / TB, TB>>>(ei);                 // 3
    k_scan1<<<SCAN_CHUNKS, 1024>>>();                               // 4 <- profiled
    k_scan2<<<1, 128>>>();                                          // 5
    k_scan3<<<nblkN, TB>>>(x);                                      // 6
    k_fill<<<(N_EDGES / 2 + TB - 1) / TB, TB>>>(ei);                // 7

    k_l1<<<fusedGrid, TB>>>(W1, b1);                                // 8
    k_l2<<<fusedGrid, TB>>>(W2, b2);                                // 9
    k_l3<<<nblkW, TB>>>(batch);                                     // 10
    k_final<<<N_GRAPHS, 128>>>(W3, b3, Wl, bl, out);                // 11
}

// round 15
// speedup vs baseline: 1.3118x; 1.3118x over previous
#include <cuda_runtime.h>
#include <cuda_fp16.h>
#include <math.h>

#define N_NODES 100000
#define N_EDGES 3200000
#define N_GRAPHS 128
#define SCAN_CHUNKS 98            // ceil(100000/1024)
#define H2ONE 0x3C003C00u         // half2(1.0, 1.0)

// ---------------- device scratch ----------------
__device__ int   g_is64;
__device__ int   g_cnt[N_NODES];
__device__ float g_dinv[N_NODES];
__device__ int   g_rowptr[N_NODES + 1];
__device__ int   g_cursor[N_NODES];
__device__ int   g_edge[N_EDGES];           // src only
__device__ float g_agg[N_NODES * 64];       // fp32 aggregation output
__device__ uint2 g_x8[N_NODES * 4];         // e4m3 dinv-scaled x, 32B/row (20+pad)
__device__ uint2 g_h8a[N_NODES * 8];        // e4m3 dinv-scaled h~1, 64B/row
__device__ uint2 g_h8b[N_NODES * 8];        // e4m3 dinv-scaled h~2, 64B/row
__device__ float g_psum[N_GRAPHS * 64];
__device__ int   g_start[N_GRAPHS + 1];
__device__ int   g_bsum[128];
__device__ int   g_boff[128];

// ---------------- helpers ----------------
__device__ __forceinline__ int ld_idx(const void* p, long long i) {
    if (g_is64) return (int)((const long long*)p)[i];
    return ((const int*)p)[i];
}

// pack two floats -> e4m3x2 (lo = first arg)
__device__ __forceinline__ unsigned fp8x2(float lo, float hi) {
    unsigned short r;
    asm("cvt.rn.satfinite.e4m3x2.f32 %0, %1, %2;" : "=h"(r) : "f"(hi), "f"(lo));
    return (unsigned)r;
}

// 4 fp8 in u32 -> two half2 cvt -> two HFMA2 into acc[0..1] (u32-held half2)
__device__ __forceinline__ void hfma2_fp8x4(unsigned* acc, unsigned u, unsigned w2) {
    unsigned lo, hi;
    unsigned short ul = (unsigned short)(u & 0xFFFFu);
    unsigned short uh = (unsigned short)(u >> 16);
    asm("cvt.rn.f16x2.e4m3x2 %0, %1;" : "=r"(lo) : "h"(ul));
    asm("cvt.rn.f16x2.e4m3x2 %0, %1;" : "=r"(hi) : "h"(uh));
    __half2 a = __hfma2(*(__half2*)&lo, *(__half2*)&w2, *(__half2*)&acc[0]);
    __half2 b = __hfma2(*(__half2*)&hi, *(__half2*)&w2, *(__half2*)&acc[1]);
    acc[0] = *(unsigned*)&a;
    acc[1] = *(unsigned*)&b;
}

__device__ __forceinline__ void hadd2_red(unsigned* acc, int n, int off) {
    for (int j = 0; j < n; j++) {
        unsigned o = __shfl_xor_sync(0xFFFFFFFFu, acc[j], off);
        __half2 s = __hadd2(*(__half2*)&acc[j], *(__half2*)&o);
        acc[j] = *(unsigned*)&s;
    }
}

// ---------------- prep: dtype probe (thread 0) + zero counters ----------------
__global__ void k_prep(const void* p) {
    int i = blockIdx.x * blockDim.x + threadIdx.x;
    if (i == 0) {
        const long long* q = (const long long*)p;
        int ok64 = 1;
        for (int k = 0; k < 256; k++) {
            long long v = q[k];
            if (v < 0 || v >= (long long)N_NODES) { ok64 = 0; break; }
        }
        g_is64 = ok64;
    }
    if (i < N_NODES) g_cnt[i] = 0;
    if (i < N_GRAPHS * 64) g_psum[i] = 0.f;
}

// ---------------- graph boundaries (batch sorted, no atomics) ----------------
__global__ void k_bound(const void* p) {
    int i = blockIdx.x * blockDim.x + threadIdx.x;
    if (i >= N_NODES) return;
    int b = ld_idx(p, i);
    int prev = (i == 0) ? -1 : ld_idx(p, i - 1);
    for (int g = prev + 1; g <= b; g++) g_start[g] = i;
    if (i == N_NODES - 1)
        for (int g = b + 1; g <= N_GRAPHS; g++) g_start[g] = N_NODES;
}

// ---------------- degree count: 4 edges/thread, fire-and-forget atomics -------
__global__ void k_deg(const void* p) {
    int t = blockIdx.x * blockDim.x + threadIdx.x;
    if (t >= N_EDGES / 4) return;
    int d0, d1, d2, d3;
    if (g_is64) {
        const longlong2* q = (const longlong2*)((const long long*)p + N_EDGES);
        longlong2 a = __ldg(&q[2 * t]);
        longlong2 b = __ldg(&q[2 * t + 1]);
        d0 = (int)a.x; d1 = (int)a.y; d2 = (int)b.x; d3 = (int)b.y;
    } else {
        const int4* q = (const int4*)((const int*)p + N_EDGES);
        int4 v = __ldg(&q[t]);
        d0 = v.x; d1 = v.y; d2 = v.z; d3 = v.w;
    }
    atomicAdd(&g_cnt[d0], 1);
    atomicAdd(&g_cnt[d1], 1);
    atomicAdd(&g_cnt[d2], 1);
    atomicAdd(&g_cnt[d3], 1);
}

// ---------------- multi-block scan ----------------
__global__ __launch_bounds__(1024) void k_scan1() {
    int tid = threadIdx.x;
    int lane = tid & 31, wid = tid >> 5;
    int i = blockIdx.x * 1024 + tid;
    int v = (i < N_NODES) ? g_cnt[i] : 0;
    int x = v;
    #pragma unroll
    for (int off = 1; off < 32; off <<= 1) {
        int t = __shfl_up_sync(0xFFFFFFFFu, x, off);
        if (lane >= off) x += t;
    }
    __shared__ int ws[32];
    if (lane == 31) ws[wid] = x;
    __syncthreads();
    if (wid == 0) {
        int y = ws[lane];
        #pragma unroll
        for (int off = 1; off < 32; off <<= 1) {
            int t = __shfl_up_sync(0xFFFFFFFFu, y, off);
            if (lane >= off) y += t;
        }
        ws[lane] = y;
    }
    __syncthreads();
    int incl = x + (wid > 0 ? ws[wid - 1] : 0);
    if (i < N_NODES) g_rowptr[i] = incl - v;
    if (tid == 1023) g_bsum[blockIdx.x] = incl;
}

__global__ void k_scan2() {
    __shared__ int sh[128];
    int t = threadIdx.x;
    int v = (t < SCAN_CHUNKS) ? g_bsum[t] : 0;
    sh[t] = v;
    __syncthreads();
    #pragma unroll
    for (int off = 1; off < 128; off <<= 1) {
        int u = (t >= off) ? sh[t - off] : 0;
        __syncthreads();
        sh[t] += u;
        __syncthreads();
    }
    if (t < SCAN_CHUNKS) g_boff[t] = sh[t] - v;
    if (t == 127) g_rowptr[N_NODES] = sh[127];
}

// ---------------- scan3: finalize rowptr/cursor/dinv + build x~ fp8 ------------
__global__ void k_scan3(const float* __restrict__ x) {
    int i = blockIdx.x * blockDim.x + threadIdx.x;
    if (i >= N_NODES) return;
    int r = g_rowptr[i] + g_boff[i >> 10];
    g_rowptr[i] = r;
    g_cursor[i] = r;
    float di = rsqrtf((float)g_cnt[i] + 1.0f);
    g_dinv[i] = di;
    const float4* xr = (const float4*)(x + i * 20);   // 80B row, 16B aligned
    float t[20];
    #pragma unroll
    for (int q = 0; q < 5; q++) {
        float4 v = __ldg(&xr[q]);
        t[4*q] = v.x; t[4*q+1] = v.y; t[4*q+2] = v.z; t[4*q+3] = v.w;
    }
    unsigned u[5];
    #pragma unroll
    for (int q = 0; q < 5; q++) {
        u[q] = fp8x2(di * t[4*q], di * t[4*q+1])
             | (fp8x2(di * t[4*q+2], di * t[4*q+3]) << 16);
    }
    g_x8[i * 4 + 0] = make_uint2(u[0], u[1]);
    g_x8[i * 4 + 1] = make_uint2(u[2], u[3]);
    g_x8[i * 4 + 2] = make_uint2(u[4], 0u);
    g_x8[i * 4 + 3] = make_uint2(0u, 0u);
}

// ---------------- CSR fill: src only ----------------
__global__ void k_fill(const void* p) {
    int t = blockIdx.x * blockDim.x + threadIdx.x;
    if (t >= N_EDGES / 2) return;
    int s0, s1, d0, d1;
    if (g_is64) {
        const longlong2* qs = (const longlong2*)p;
        const longlong2* qd = (const longlong2*)((const long long*)p + N_EDGES);
        longlong2 sv = __ldg(&qs[t]);
        longlong2 dv = __ldg(&qd[t]);
        s0 = (int)sv.x; s1 = (int)sv.y;
        d0 = (int)dv.x; d1 = (int)dv.y;
    } else {
        const int2* qs = (const int2*)p;
        const int2* qd = (const int2*)((const int*)p + N_EDGES);
        int2 sv = __ldg(&qs[t]);
        int2 dv = __ldg(&qd[t]);
        s0 = sv.x; s1 = sv.y;
        d0 = dv.x; d1 = dv.y;
    }
    int p0 = atomicAdd(&g_cursor[d0], 1);
    g_edge[p0] = s0;
    int p1 = atomicAdd(&g_cursor[d1], 1);
    g_edge[p1] = s1;
}

// ---------------- aggregation F=20 on fp8 x~ (32B rows, 1 sector/edge) ---------
// 8 edge-groups of 4 lanes; lane's 8B chunk = 8 features as 4 fp8-u32 halves.
__global__ __launch_bounds__(256) void k_agg20() {
    int i = (blockIdx.x * blockDim.x + threadIdx.x) >> 5;
    int lane = threadIdx.x & 31;
    int eg = lane >> 2, fl = lane & 3;
    int beg = g_rowptr[i], end = g_rowptr[i + 1];
    unsigned acc[4] = {0u, 0u, 0u, 0u};   // 8 features as 4 half2
    for (int e = beg; e < end; e += 16) {
        int e0 = e + eg, e1 = e + 8 + eg;
        int s0 = g_edge[(e0 < end) ? e0 : beg];
        int s1 = g_edge[(e1 < end) ? e1 : beg];
        unsigned w0 = (e0 < end) ? H2ONE : 0u;
        unsigned w1 = (e1 < end) ? H2ONE : 0u;
        uint2 v0 = __ldg(&g_x8[s0 * 4 + fl]);
        uint2 v1 = __ldg(&g_x8[s1 * 4 + fl]);
        hfma2_fp8x4(acc + 0, v0.x, w0);
        hfma2_fp8x4(acc + 2, v0.y, w0);
        hfma2_fp8x4(acc + 0, v1.x, w1);
        hfma2_fp8x4(acc + 2, v1.y, w1);
    }
    hadd2_red(acc, 4, 4);
    hadd2_red(acc, 4, 8);
    hadd2_red(acc, 4, 16);
    if (eg == 0 && fl < 3) {
        uint2 sv = g_x8[i * 4 + fl];       // self-loop
        hfma2_fp8x4(acc + 0, sv.x, H2ONE);
        hfma2_fp8x4(acc + 2, sv.y, H2ONE);
        float di = g_dinv[i];
        float o[8];
        #pragma unroll
        for (int j = 0; j < 4; j++) {
            float2 f = __half22float2(*(__half2*)&acc[j]);
            o[2*j] = di * f.x; o[2*j+1] = di * f.y;
        }
        int f0 = fl * 8;
        *(float4*)&g_agg[i * 20 + f0] = make_float4(o[0], o[1], o[2], o[3]);
        if (fl < 2)
            *(float4*)&g_agg[i * 20 + f0 + 4] = make_float4(o[4], o[5], o[6], o[7]);
    }
}

// ---------------- aggregation F=64 on fp8 h~ (64B rows, 2 sectors/edge) --------
// 4 edge-groups of 8 lanes; lane's 8B chunk = 8 features.
template <bool POOL>
__device__ __forceinline__ void agg64_body(const uint2* __restrict__ src,
                                           const void* batch) {
    __shared__ float sacc[64];
    __shared__ int sg;
    int i = (blockIdx.x * blockDim.x + threadIdx.x) >> 5;   // grid exact
    int lane = threadIdx.x & 31;
    int eg = lane >> 3, fl = lane & 7;
    if (POOL) {
        if (threadIdx.x < 64) sacc[threadIdx.x] = 0.f;
        if (threadIdx.x == 0) sg = ld_idx(batch, (blockIdx.x * blockDim.x) >> 5);
        __syncthreads();
    }
    int beg = g_rowptr[i], end = g_rowptr[i + 1];
    unsigned acc[4] = {0u, 0u, 0u, 0u};
    for (int e = beg; e < end; e += 8) {
        int e0 = e + eg, e1 = e + 4 + eg;
        int s0 = g_edge[(e0 < end) ? e0 : beg];
        int s1 = g_edge[(e1 < end) ? e1 : beg];
        unsigned w0 = (e0 < end) ? H2ONE : 0u;
        unsigned w1 = (e1 < end) ? H2ONE : 0u;
        uint2 v0 = __ldg(&src[s0 * 8 + fl]);
        uint2 v1 = __ldg(&src[s1 * 8 + fl]);
        hfma2_fp8x4(acc + 0, v0.x, w0);
        hfma2_fp8x4(acc + 2, v0.y, w0);
        hfma2_fp8x4(acc + 0, v1.x, w1);
        hfma2_fp8x4(acc + 2, v1.y, w1);
    }
    hadd2_red(acc, 4, 8);
    hadd2_red(acc, 4, 16);
    // self-loop + dinv scale (all eg groups hold identical reduced sums)
    uint2 sv = src[i * 8 + fl];
    hfma2_fp8x4(acc + 0, sv.x, H2ONE);
    hfma2_fp8x4(acc + 2, sv.y, H2ONE);
    float di = g_dinv[i];
    float o[8];
    #pragma unroll
    for (int j = 0; j < 4; j++) {
        float2 f = __half22float2(*(__half2*)&acc[j]);
        o[2*j] = di * f.x; o[2*j+1] = di * f.y;
    }
    if (!POOL) {
        if (eg == 0) {
            *(float4*)&g_agg[i * 64 + fl * 8]     = make_float4(o[0], o[1], o[2], o[3]);
            *(float4*)&g_agg[i * 64 + fl * 8 + 4] = make_float4(o[4], o[5], o[6], o[7]);
        }
    } else {
        int b = ld_idx(batch, i);
        int uniform = __syncthreads_and(b == sg);
        if (uniform) {
            if (eg == 0) {
                #pragma unroll
                for (int j = 0; j < 8; j++)
                    atomicAdd(&sacc[fl * 8 + j], o[j]);
            }
            __syncthreads();
            if (threadIdx.x < 64)
                atomicAdd(&g_psum[sg * 64 + threadIdx.x], sacc[threadIdx.x]);
        } else {
            if (eg == 0) {
                #pragma unroll
                for (int j = 0; j < 8; j++)
                    atomicAdd(&g_psum[b * 64 + fl * 8 + j], o[j]);
            }
        }
    }
}

__global__ __launch_bounds__(256) void k_agg64a() { agg64_body<false>(g_h8a, nullptr); }
__global__ __launch_bounds__(256) void k_agg64_pool(const void* batch) {
    agg64_body<true>(g_h8b, batch);
}

// ---------------- matmul: fp32 in -> fp8 h~ out (relu + dinv prescale) ---------
template <int FIN>
__device__ __forceinline__ void mm_body_8(const float* __restrict__ in,
                                          const float* __restrict__ W,
                                          const float* __restrict__ b,
                                          uint2* __restrict__ out8) {
    constexpr int FOUT = 64;
    constexpr int NT = 64;
    __shared__ float Ws[FIN * FOUT];
    __shared__ float bs[FOUT];
    __shared__ float rT[FIN][NT + 4];
    for (int k = threadIdx.x; k < FIN * FOUT; k += 256) Ws[k] = W[k];
    if (threadIdx.x < FOUT) bs[threadIdx.x] = b[threadIdx.x];
    int cg = threadIdx.x & 15;
    int ng = threadIdx.x >> 4;
    int c0 = cg * 4, nb = ng * 4;
    const int ntiles = (N_NODES + NT - 1) / NT;
    for (int tile = blockIdx.x; tile < ntiles; tile += gridDim.x) {
        int n0 = tile * NT;
        for (int idx = threadIdx.x; idx < NT * FIN; idx += 256) {
            int n = idx / FIN, k = idx - n * FIN;
            int node = n0 + n;
            rT[k][n] = (node < N_NODES) ? in[node * FIN + k] : 0.f;
        }
        __syncthreads();
        float a0x = bs[c0], a0y = bs[c0+1], a0z = bs[c0+2], a0w = bs[c0+3];
        float a1x = a0x, a1y = a0y, a1z = a0z, a1w = a0w;
        float a2x = a0x, a2y = a0y, a2z = a0z, a2w = a0w;
        float a3x = a0x, a3y = a0y, a3z = a0z, a3w = a0w;
        #pragma unroll 4
        for (int k = 0; k < FIN; k++) {
            float4 rv = *(const float4*)&rT[k][nb];
            float4 wv = *(const float4*)&Ws[k * FOUT + c0];
            a0x = fmaf(rv.x, wv.x, a0x); a0y = fmaf(rv.x, wv.y, a0y);
            a0z = fmaf(rv.x, wv.z, a0z); a0w = fmaf(rv.x, wv.w, a0w);
            a1x = fmaf(rv.y, wv.x, a1x); a1y = fmaf(rv.y, wv.y, a1y);
            a1z = fmaf(rv.y, wv.z, a1z); a1w = fmaf(rv.y, wv.w, a1w);
            a2x = fmaf(rv.z, wv.x, a2x); a2y = fmaf(rv.z, wv.y, a2y);
            a2z = fmaf(rv.z, wv.z, a2z); a2w = fmaf(rv.z, wv.w, a2w);
            a3x = fmaf(rv.w, wv.x, a3x); a3y = fmaf(rv.w, wv.y, a3y);
            a3z = fmaf(rv.w, wv.z, a3z); a3w = fmaf(rv.w, wv.w, a3w);
        }
        #define MM_STORE_8(NI, AX, AY, AZ, AW)                                 \
        {                                                                      \
            int node = n0 + nb + NI;                                           \
            if (node < N_NODES) {                                              \
                float di = g_dinv[node];                                       \
                unsigned lo = fp8x2(di * fmaxf(AX, 0.f), di * fmaxf(AY, 0.f)); \
                unsigned hi = fp8x2(di * fmaxf(AZ, 0.f), di * fmaxf(AW, 0.f)); \
                ((unsigned*)out8)[node * 16 + cg] = lo | (hi << 16);           \
            }                                                                  \
        }
        MM_STORE_8(0, a0x, a0y, a0z, a0w)
        MM_STORE_8(1, a1x, a1y, a1z, a1w)
        MM_STORE_8(2, a2x, a2y, a2z, a2w)
        MM_STORE_8(3, a3x, a3y, a3z, a3w)
        #undef MM_STORE_8
        __syncthreads();
    }
}

__global__ __launch_bounds__(256) void k_mm1(const float* __restrict__ W,
                                             const float* __restrict__ b) {
    mm_body_8<20>(g_agg, W, b, g_h8a);
}
__global__ __launch_bounds__(256) void k_mm2(const float* __restrict__ W,
                                             const float* __restrict__ b) {
    mm_body_8<64>(g_agg, W, b, g_h8b);
}

// ---------------- final: (mean @ W3 + b3) @ Wl + bl -> log_softmax -------------
__global__ __launch_bounds__(128) void k_final(const float* __restrict__ W3,
                                               const float* __restrict__ b3,
                                               const float* __restrict__ Wl,
                                               const float* __restrict__ bl,
                                               float* __restrict__ out) {
    int g = blockIdx.x;
    int j = threadIdx.x;
    __shared__ float sp[64];
    __shared__ float sf[128];
    int st = g_start[g], en = g_start[g + 1];
    float inv = 1.0f / fmaxf((float)(en - st), 1.0f);
    if (j < 64) sp[j] = g_psum[g * 64 + j] * inv;
    __syncthreads();
    float f = b3[j];
    #pragma unroll 8
    for (int k = 0; k < 64; k++)
        f = fmaf(sp[k], W3[k * 128 + j], f);
    sf[j] = f;
    __syncthreads();
    if (j < 32) {
        float l = -INFINITY;
        if (j < 14) {
            float acc = bl[j];
            #pragma unroll 8
            for (int k = 0; k < 128; k++)
                acc = fmaf(sf[k], Wl[k * 14 + j], acc);
            l = acc;
        }
        float m = l;
        #pragma unroll
        for (int off = 16; off; off >>= 1)
            m = fmaxf(m, __shfl_xor_sync(0xFFFFFFFFu, m, off));
        float ex = (j < 14) ? expf(l - m) : 0.f;
        float s = ex;
        #pragma unroll
        for (int off = 16; off; off >>= 1)
            s += __shfl_xor_sync(0xFFFFFFFFu, s, off);
        if (j < 14) out[g * 14 + j] = l - m - logf(s);
    }
}

// ---------------- launch ----------------
extern "C" void kernel_launch(void* const* d_in, const int* in_sizes, int n_in,
                              void* d_out, int out_size) {
    const float* x     = (const float*)d_in[0];
    const void*  ei    = d_in[1];
    const void*  batch = d_in[2];
    const float* W1 = (const float*)d_in[3];
    const float* b1 = (const float*)d_in[4];
    const float* W2 = (const float*)d_in[5];
    const float* b2 = (const float*)d_in[6];
    const float* W3 = (const float*)d_in[7];
    const float* b3 = (const float*)d_in[8];
    const float* Wl = (const float*)d_in[9];
    const float* bl = (const float*)d_in[10];
    float* out = (float*)d_out;

    const int TB = 256;
    int nblkN = (N_NODES + TB - 1) / TB;
    int nblkW = N_NODES / 8;            // exact: 100000 = 12500 * 8
    int mmGrid = 592;

    k_prep<<<nblkN, TB>>>(ei);                                      // 1
    k_bound<<<nblkN, TB>>>(batch);                                  // 2
    k_deg<<<(N_EDGES / 4 + TB - 1) / TB, TB>>>(ei);                 // 3
    k_scan1<<<SCAN_CHUNKS, 1024>>>();                               // 4 <- profiled
    k_scan2<<<1, 128>>>();                                          // 5
    k_scan3<<<nblkN, TB>>>(x);                                      // 6
    k_fill<<<(N_EDGES / 2 + TB - 1) / TB, TB>>>(ei);                // 7

    k_agg20<<<nblkW, TB>>>();                                       // 8
    k_mm1<<<mmGrid, TB>>>(W1, b1);                                  // 9
    k_agg64a<<<nblkW, TB>>>();                                      // 10
    k_mm2<<<mmGrid, TB>>>(W2, b2);                                  // 11
    k_agg64_pool<<<nblkW, TB>>>(batch);                             // 12
    k_final<<<N_GRAPHS, 128>>>(W3, b3, Wl, bl, out);                // 13
}

// round 17
// speedup vs baseline: 1.3222x; 1.0079x over previous
#include <cuda_runtime.h>
#include <cuda_fp16.h>
#include <math.h>

#define N_NODES 100000
#define N_EDGES 3200000
#define N_GRAPHS 128
#define SCAN_CHUNKS 98            // ceil(100000/1024)
#define H2ONE 0x3C003C00u         // half2(1.0, 1.0)

// ---------------- device scratch ----------------
__device__ int   g_is64;
__device__ int   g_cnt[N_NODES];
__device__ float g_dinv[N_NODES];
__device__ int   g_rowptr[N_NODES + 1];
__device__ int   g_cursor[N_NODES];
__device__ int   g_edge[N_EDGES];           // src only
__device__ float g_agg[N_NODES * 64];       // fp32 aggregation output
__device__ uint2 g_x8[N_NODES * 4];         // e4m3 dinv-scaled x, 32B/row (20+pad)
__device__ uint2 g_h8a[N_NODES * 8];        // e4m3 dinv-scaled h~1, 64B/row
__device__ uint2 g_h8b[N_NODES * 8];        // e4m3 dinv-scaled h~2, 64B/row
__device__ float g_psum[N_GRAPHS * 64];
__device__ int   g_start[N_GRAPHS + 1];
__device__ int   g_aggval[SCAN_CHUNKS];     // single-pass scan: block aggregates
__device__ int   g_aggflag[SCAN_CHUNKS];    // single-pass scan: ready flags

// ---------------- helpers ----------------
__device__ __forceinline__ int ld_idx(const void* p, long long i) {
    if (g_is64) return (int)((const long long*)p)[i];
    return ((const int*)p)[i];
}

// pack two floats -> e4m3x2 (lo = first arg)
__device__ __forceinline__ unsigned fp8x2(float lo, float hi) {
    unsigned short r;
    asm("cvt.rn.satfinite.e4m3x2.f32 %0, %1, %2;" : "=h"(r) : "f"(hi), "f"(lo));
    return (unsigned)r;
}

// 4 fp8 in u32 -> two half2 cvt -> two HFMA2 into acc[0..1] (u32-held half2)
__device__ __forceinline__ void hfma2_fp8x4(unsigned* acc, unsigned u, unsigned w2) {
    unsigned lo, hi;
    unsigned short ul = (unsigned short)(u & 0xFFFFu);
    unsigned short uh = (unsigned short)(u >> 16);
    asm("cvt.rn.f16x2.e4m3x2 %0, %1;" : "=r"(lo) : "h"(ul));
    asm("cvt.rn.f16x2.e4m3x2 %0, %1;" : "=r"(hi) : "h"(uh));
    __half2 a = __hfma2(*(__half2*)&lo, *(__half2*)&w2, *(__half2*)&acc[0]);
    __half2 b = __hfma2(*(__half2*)&hi, *(__half2*)&w2, *(__half2*)&acc[1]);
    acc[0] = *(unsigned*)&a;
    acc[1] = *(unsigned*)&b;
}

__device__ __forceinline__ void hadd2_red(unsigned* acc, int n, int off) {
    for (int j = 0; j < n; j++) {
        unsigned o = __shfl_xor_sync(0xFFFFFFFFu, acc[j], off);
        __half2 s = __hadd2(*(__half2*)&acc[j], *(__half2*)&o);
        acc[j] = *(unsigned*)&s;
    }
}

// ---------------- prep: dtype probe + zero counters + zero scan flags ----------
__global__ void k_prep(const void* p) {
    int i = blockIdx.x * blockDim.x + threadIdx.x;
    if (i == 0) {
        const long long* q = (const long long*)p;
        int ok64 = 1;
        for (int k = 0; k < 256; k++) {
            long long v = q[k];
            if (v < 0 || v >= (long long)N_NODES) { ok64 = 0; break; }
        }
        g_is64 = ok64;
    }
    if (i < N_NODES) g_cnt[i] = 0;
    if (i < N_GRAPHS * 64) g_psum[i] = 0.f;
    if (i < SCAN_CHUNKS) g_aggflag[i] = 0;
}

// ---------------- degree count (4 edges/thread) + graph boundaries folded ------
__global__ void k_deg(const void* p, const void* batch) {
    int t = blockIdx.x * blockDim.x + threadIdx.x;
    // folded bound work: batch is sorted -> graph start offsets, no atomics
    if (t < N_NODES) {
        int b = ld_idx(batch, t);
        int prev = (t == 0) ? -1 : ld_idx(batch, t - 1);
        for (int g = prev + 1; g <= b; g++) g_start[g] = t;
        if (t == N_NODES - 1)
            for (int g = b + 1; g <= N_GRAPHS; g++) g_start[g] = N_NODES;
    }
    if (t >= N_EDGES / 4) return;
    int d0, d1, d2, d3;
    if (g_is64) {
        const longlong2* q = (const longlong2*)((const long long*)p + N_EDGES);
        longlong2 a = __ldg(&q[2 * t]);
        longlong2 b = __ldg(&q[2 * t + 1]);
        d0 = (int)a.x; d1 = (int)a.y; d2 = (int)b.x; d3 = (int)b.y;
    } else {
        const int4* q = (const int4*)((const int*)p + N_EDGES);
        int4 v = __ldg(&q[t]);
        d0 = v.x; d1 = v.y; d2 = v.z; d3 = v.w;
    }
    atomicAdd(&g_cnt[d0], 1);
    atomicAdd(&g_cnt[d1], 1);
    atomicAdd(&g_cnt[d2], 1);
    atomicAdd(&g_cnt[d3], 1);
}

// ---------------- single-pass scan + dinv + x~ fp8 conversion ------------------
// 98 blocks, all co-resident: each block publishes its aggregate immediately,
// then one warp spin-sums predecessors' aggregates (no serialized chain).
__global__ __launch_bounds__(1024) void k_scan(const float* __restrict__ x) {
    int tid = threadIdx.x;
    int lane = tid & 31, wid = tid >> 5;
    int b = blockIdx.x;
    int i = b * 1024 + tid;
    int v = (i < N_NODES) ? g_cnt[i] : 0;
    int xs = v;
    #pragma unroll
    for (int off = 1; off < 32; off <<= 1) {
        int t = __shfl_up_sync(0xFFFFFFFFu, xs, off);
        if (lane >= off) xs += t;
    }
    __shared__ int ws[32];
    __shared__ int s_prefix;
    if (lane == 31) ws[wid] = xs;
    __syncthreads();
    if (wid == 0) {
        int y = ws[lane];
        #pragma unroll
        for (int off = 1; off < 32; off <<= 1) {
            int t = __shfl_up_sync(0xFFFFFFFFu, y, off);
            if (lane >= off) y += t;
        }
        ws[lane] = y;
    }
    __syncthreads();
    int incl = xs + (wid > 0 ? ws[wid - 1] : 0);   // block-local inclusive
    int bsum = ws[31];                              // block total
    // publish aggregate
    if (tid == 0) {
        g_aggval[b] = bsum;
        __threadfence();
        atomicExch(&g_aggflag[b], 1);
    }
    // warp 0: sum predecessors' aggregates (deterministic fixed-order sum)
    if (wid == 0) {
        int sum = 0;
        for (int j = lane; j < b; j += 32) {
            while (atomicAdd(&g_aggflag[j], 0) == 0) { }
            sum += g_aggval[j];
        }
        #pragma unroll
        for (int off = 16; off; off >>= 1)
            sum += __shfl_xor_sync(0xFFFFFFFFu, sum, off);
        if (lane == 0) s_prefix = sum;
    }
    __syncthreads();
    int prefix = s_prefix;
    if (i < N_NODES) {
        int r = prefix + incl - v;                 // global exclusive
        g_rowptr[i] = r;
        g_cursor[i] = r;
        float di = rsqrtf((float)v + 1.0f);
        g_dinv[i] = di;
        // x~ row: 20 floats * di -> fp8, padded to 32 bytes
        const float4* xr = (const float4*)(x + i * 20);
        float t[20];
        #pragma unroll
        for (int q = 0; q < 5; q++) {
            float4 vv = __ldg(&xr[q]);
            t[4*q] = vv.x; t[4*q+1] = vv.y; t[4*q+2] = vv.z; t[4*q+3] = vv.w;
        }
        unsigned u[5];
        #pragma unroll
        for (int q = 0; q < 5; q++) {
            u[q] = fp8x2(di * t[4*q], di * t[4*q+1])
                 | (fp8x2(di * t[4*q+2], di * t[4*q+3]) << 16);
        }
        g_x8[i * 4 + 0] = make_uint2(u[0], u[1]);
        g_x8[i * 4 + 1] = make_uint2(u[2], u[3]);
        g_x8[i * 4 + 2] = make_uint2(u[4], 0u);
        g_x8[i * 4 + 3] = make_uint2(0u, 0u);
    }
    if (b == SCAN_CHUNKS - 1 && tid == 1023)
        g_rowptr[N_NODES] = prefix + incl;
}

// ---------------- CSR fill: src only ----------------
__global__ void k_fill(const void* p) {
    int t = blockIdx.x * blockDim.x + threadIdx.x;
    if (t >= N_EDGES / 2) return;
    int s0, s1, d0, d1;
    if (g_is64) {
        const longlong2* qs = (const longlong2*)p;
        const longlong2* qd = (const longlong2*)((const long long*)p + N_EDGES);
        longlong2 sv = __ldg(&qs[t]);
        longlong2 dv = __ldg(&qd[t]);
        s0 = (int)sv.x; s1 = (int)sv.y;
        d0 = (int)dv.x; d1 = (int)dv.y;
    } else {
        const int2* qs = (const int2*)p;
        const int2* qd = (const int2*)((const int*)p + N_EDGES);
        int2 sv = __ldg(&qs[t]);
        int2 dv = __ldg(&qd[t]);
        s0 = sv.x; s1 = sv.y;
        d0 = dv.x; d1 = dv.y;
    }
    int p0 = atomicAdd(&g_cursor[d0], 1);
    g_edge[p0] = s0;
    int p1 = atomicAdd(&g_cursor[d1], 1);
    g_edge[p1] = s1;
}

// ---------------- aggregation F=20 on fp8 x~ (32B rows, 1 sector/edge) ---------
__global__ __launch_bounds__(256) void k_agg20() {
    int i = (blockIdx.x * blockDim.x + threadIdx.x) >> 5;
    int lane = threadIdx.x & 31;
    int eg = lane >> 2, fl = lane & 3;
    int beg = g_rowptr[i], end = g_rowptr[i + 1];
    unsigned acc[4] = {0u, 0u, 0u, 0u};   // 8 features as 4 half2
    for (int e = beg; e < end; e += 16) {
        int e0 = e + eg, e1 = e + 8 + eg;
        int s0 = g_edge[(e0 < end) ? e0 : beg];
        int s1 = g_edge[(e1 < end) ? e1 : beg];
        unsigned w0 = (e0 < end) ? H2ONE : 0u;
        unsigned w1 = (e1 < end) ? H2ONE : 0u;
        uint2 v0 = __ldg(&g_x8[s0 * 4 + fl]);
        uint2 v1 = __ldg(&g_x8[s1 * 4 + fl]);
        hfma2_fp8x4(acc + 0, v0.x, w0);
        hfma2_fp8x4(acc + 2, v0.y, w0);
        hfma2_fp8x4(acc + 0, v1.x, w1);
        hfma2_fp8x4(acc + 2, v1.y, w1);
    }
    hadd2_red(acc, 4, 4);
    hadd2_red(acc, 4, 8);
    hadd2_red(acc, 4, 16);
    if (eg == 0 && fl < 3) {
        uint2 sv = g_x8[i * 4 + fl];       // self-loop
        hfma2_fp8x4(acc + 0, sv.x, H2ONE);
        hfma2_fp8x4(acc + 2, sv.y, H2ONE);
        float di = g_dinv[i];
        float o[8];
        #pragma unroll
        for (int j = 0; j < 4; j++) {
            float2 f = __half22float2(*(__half2*)&acc[j]);
            o[2*j] = di * f.x; o[2*j+1] = di * f.y;
        }
        int f0 = fl * 8;
        *(float4*)&g_agg[i * 20 + f0] = make_float4(o[0], o[1], o[2], o[3]);
        if (fl < 2)
            *(float4*)&g_agg[i * 20 + f0 + 4] = make_float4(o[4], o[5], o[6], o[7]);
    }
}

// ---------------- aggregation F=64 on fp8 h~ (64B rows, 2 sectors/edge) --------
template <bool POOL>
__device__ __forceinline__ void agg64_body(const uint2* __restrict__ src,
                                           const void* batch) {
    __shared__ float sacc[64];
    __shared__ int sg;
    int i = (blockIdx.x * blockDim.x + threadIdx.x) >> 5;   // grid exact
    int lane = threadIdx.x & 31;
    int eg = lane >> 3, fl = lane & 7;
    if (POOL) {
        if (threadIdx.x < 64) sacc[threadIdx.x] = 0.f;
        if (threadIdx.x == 0) sg = ld_idx(batch, (blockIdx.x * blockDim.x) >> 5);
        __syncthreads();
    }
    int beg = g_rowptr[i], end = g_rowptr[i + 1];
    unsigned acc[4] = {0u, 0u, 0u, 0u};
    for (int e = beg; e < end; e += 8) {
        int e0 = e + eg, e1 = e + 4 + eg;
        int s0 = g_edge[(e0 < end) ? e0 : beg];
        int s1 = g_edge[(e1 < end) ? e1 : beg];
        unsigned w0 = (e0 < end) ? H2ONE : 0u;
        unsigned w1 = (e1 < end) ? H2ONE : 0u;
        uint2 v0 = __ldg(&src[s0 * 8 + fl]);
        uint2 v1 = __ldg(&src[s1 * 8 + fl]);
        hfma2_fp8x4(acc + 0, v0.x, w0);
        hfma2_fp8x4(acc + 2, v0.y, w0);
        hfma2_fp8x4(acc + 0, v1.x, w1);
        hfma2_fp8x4(acc + 2, v1.y, w1);
    }
    hadd2_red(acc, 4, 8);
    hadd2_red(acc, 4, 16);
    uint2 sv = src[i * 8 + fl];            // self-loop
    hfma2_fp8x4(acc + 0, sv.x, H2ONE);
    hfma2_fp8x4(acc + 2, sv.y, H2ONE);
    float di = g_dinv[i];
    float o[8];
    #pragma unroll
    for (int j = 0; j < 4; j++) {
        float2 f = __half22float2(*(__half2*)&acc[j]);
        o[2*j] = di * f.x; o[2*j+1] = di * f.y;
    }
    if (!POOL) {
        if (eg == 0) {
            *(float4*)&g_agg[i * 64 + fl * 8]     = make_float4(o[0], o[1], o[2], o[3]);
            *(float4*)&g_agg[i * 64 + fl * 8 + 4] = make_float4(o[4], o[5], o[6], o[7]);
        }
    } else {
        int b = ld_idx(batch, i);
        int uniform = __syncthreads_and(b == sg);
        if (uniform) {
            if (eg == 0) {
                #pragma unroll
                for (int j = 0; j < 8; j++)
                    atomicAdd(&sacc[fl * 8 + j], o[j]);
            }
            __syncthreads();
            if (threadIdx.x < 64)
                atomicAdd(&g_psum[sg * 64 + threadIdx.x], sacc[threadIdx.x]);
        } else {
            if (eg == 0) {
                #pragma unroll
                for (int j = 0; j < 8; j++)
                    atomicAdd(&g_psum[b * 64 + fl * 8 + j], o[j]);
            }
        }
    }
}

__global__ __launch_bounds__(256) void k_agg64a() { agg64_body<false>(g_h8a, nullptr); }
__global__ __launch_bounds__(256) void k_agg64_pool(const void* batch) {
    agg64_body<true>(g_h8b, batch);
}

// ---------------- matmul: fp32 in -> fp8 h~ out (relu + dinv prescale) ---------
template <int FIN>
__device__ __forceinline__ void mm_body_8(const float* __restrict__ in,
                                          const float* __restrict__ W,
                                          const float* __restrict__ b,
                                          uint2* __restrict__ out8) {
    constexpr int FOUT = 64;
    constexpr int NT = 64;
    __shared__ float Ws[FIN * FOUT];
    __shared__ float bs[FOUT];
    __shared__ float rT[FIN][NT + 4];
    for (int k = threadIdx.x; k < FIN * FOUT; k += 256) Ws[k] = W[k];
    if (threadIdx.x < FOUT) bs[threadIdx.x] = b[threadIdx.x];
    int cg = threadIdx.x & 15;
    int ng = threadIdx.x >> 4;
    int c0 = cg * 4, nb = ng * 4;
    const int ntiles = (N_NODES + NT - 1) / NT;
    for (int tile = blockIdx.x; tile < ntiles; tile += gridDim.x) {
        int n0 = tile * NT;
        for (int idx = threadIdx.x; idx < NT * FIN; idx += 256) {
            int n = idx / FIN, k = idx - n * FIN;
            int node = n0 + n;
            rT[k][n] = (node < N_NODES) ? in[node * FIN + k] : 0.f;
        }
        __syncthreads();
        float a0x = bs[c0], a0y = bs[c0+1], a0z = bs[c0+2], a0w = bs[c0+3];
        float a1x = a0x, a1y = a0y, a1z = a0z, a1w = a0w;
        float a2x = a0x, a2y = a0y, a2z = a0z, a2w = a0w;
        float a3x = a0x, a3y = a0y, a3z = a0z, a3w = a0w;
        #pragma unroll 4
        for (int k = 0; k < FIN; k++) {
            float4 rv = *(const float4*)&rT[k][nb];
            float4 wv = *(const float4*)&Ws[k * FOUT + c0];
            a0x = fmaf(rv.x, wv.x, a0x); a0y = fmaf(rv.x, wv.y, a0y);
            a0z = fmaf(rv.x, wv.z, a0z); a0w = fmaf(rv.x, wv.w, a0w);
            a1x = fmaf(rv.y, wv.x, a1x); a1y = fmaf(rv.y, wv.y, a1y);
            a1z = fmaf(rv.y, wv.z, a1z); a1w = fmaf(rv.y, wv.w, a1w);
            a2x = fmaf(rv.z, wv.x, a2x); a2y = fmaf(rv.z, wv.y, a2y);
            a2z = fmaf(rv.z, wv.z, a2z); a2w = fmaf(rv.z, wv.w, a2w);
            a3x = fmaf(rv.w, wv.x, a3x); a3y = fmaf(rv.w, wv.y, a3y);
            a3z = fmaf(rv.w, wv.z, a3z); a3w = fmaf(rv.w, wv.w, a3w);
        }
        #define MM_STORE_8(NI, AX, AY, AZ, AW)                                 \
        {                                                                      \
            int node = n0 + nb + NI;                                           \
            if (node < N_NODES) {                                              \
                float di = g_dinv[node];                                       \
                unsigned lo = fp8x2(di * fmaxf(AX, 0.f), di * fmaxf(AY, 0.f)); \
                unsigned hi = fp8x2(di * fmaxf(AZ, 0.f), di * fmaxf(AW, 0.f)); \
                ((unsigned*)out8)[node * 16 + cg] = lo | (hi << 16);           \
            }                                                                  \
        }
        MM_STORE_8(0, a0x, a0y, a0z, a0w)
        MM_STORE_8(1, a1x, a1y, a1z, a1w)
        MM_STORE_8(2, a2x, a2y, a2z, a2w)
        MM_STORE_8(3, a3x, a3y, a3z, a3w)
        #undef MM_STORE_8
        __syncthreads();
    }
}

__global__ __launch_bounds__(256) void k_mm1(const float* __restrict__ W,
                                             const float* __restrict__ b) {
    mm_body_8<20>(g_agg, W, b, g_h8a);
}
__global__ __launch_bounds__(256) void k_mm2(const float* __restrict__ W,
                                             const float* __restrict__ b) {
    mm_body_8<64>(g_agg, W, b, g_h8b);
}

// ---------------- final: (mean @ W3 + b3) @ Wl + bl -> log_softmax -------------
__global__ __launch_bounds__(128) void k_final(const float* __restrict__ W3,
                                               const float* __restrict__ b3,
                                               const float* __restrict__ Wl,
                                               const float* __restrict__ bl,
                                               float* __restrict__ out) {
    int g = blockIdx.x;
    int j = threadIdx.x;
    __shared__ float sp[64];
    __shared__ float sf[128];
    int st = g_start[g], en = g_start[g + 1];
    float inv = 1.0f / fmaxf((float)(en - st), 1.0f);
    if (j < 64) sp[j] = g_psum[g * 64 + j] * inv;
    __syncthreads();
    float f = b3[j];
    #pragma unroll 8
    for (int k = 0; k < 64; k++)
        f = fmaf(sp[k], W3[k * 128 + j], f);
    sf[j] = f;
    __syncthreads();
    if (j < 32) {
        float l = -INFINITY;
        if (j < 14) {
            float acc = bl[j];
            #pragma unroll 8
            for (int k = 0; k < 128; k++)
                acc = fmaf(sf[k], Wl[k * 14 + j], acc);
            l = acc;
        }
        float m = l;
        #pragma unroll
        for (int off = 16; off; off >>= 1)
            m = fmaxf(m, __shfl_xor_sync(0xFFFFFFFFu, m, off));
        float ex = (j < 14) ? expf(l - m) : 0.f;
        float s = ex;
        #pragma unroll
        for (int off = 16; off; off >>= 1)
            s += __shfl_xor_sync(0xFFFFFFFFu, s, off);
        if (j < 14) out[g * 14 + j] = l - m - logf(s);
    }
}

// ---------------- launch ----------------
extern "C" void kernel_launch(void* const* d_in, const int* in_sizes, int n_in,
                              void* d_out, int out_size) {
    const float* x     = (const float*)d_in[0];
    const void*  ei    = d_in[1];
    const void*  batch = d_in[2];
    const float* W1 = (const float*)d_in[3];
    const float* b1 = (const float*)d_in[4];
    const float* W2 = (const float*)d_in[5];
    const float* b2 = (const float*)d_in[6];
    const float* W3 = (const float*)d_in[7];
    const float* b3 = (const float*)d_in[8];
    const float* Wl = (const float*)d_in[9];
    const float* bl = (const float*)d_in[10];
    float* out = (float*)d_out;

    const int TB = 256;
    int nblkN = (N_NODES + TB - 1) / TB;
    int nblkW = N_NODES / 8;            // exact: 100000 = 12500 * 8
    int mmGrid = 592;

    k_prep<<<nblkN, TB>>>(ei);                                      // 1
    k_deg<<<(N_EDGES / 4 + TB - 1) / TB, TB>>>(ei, batch);          // 2
    k_scan<<<SCAN_CHUNKS, 1024>>>(x);                               // 3
    k_fill<<<(N_EDGES / 2 + TB - 1) / TB, TB>>>(ei);                // 4 <- profiled
    k_agg20<<<nblkW, TB>>>();                                       // 5
    k_mm1<<<mmGrid, TB>>>(W1, b1);                                  // 6
    k_agg64a<<<nblkW, TB>>>();                                      // 7
    k_mm2<<<mmGrid, TB>>>(W2, b2);                                  // 8
    k_agg64_pool<<<nblkW, TB>>>(batch);                             // 9
    k_final<<<N_GRAPHS, 128>>>(W3, b3, Wl, bl, out);                // 10
}